// round 1
// baseline (speedup 1.0000x reference)
#include <cuda_runtime.h>
#include <cstdint>

#define D_MODEL 1024
#define NQ      1024
#define NKV     4096
#define BATCH   4
#define NHEADS  16
#define HDIM    64

// ---------------- scratch (device globals: allocation-free) ----------------
__device__ float g_qp[(size_t)BATCH * NQ  * D_MODEL];   // 16 MB  [B,Nq,D] scaled
__device__ float g_k [(size_t)BATCH * NKV * D_MODEL];   // 64 MB  [B,Nkv,D]
__device__ float g_v [(size_t)BATCH * NKV * D_MODEL];   // 64 MB
__device__ float g_x [(size_t)BATCH * NQ  * D_MODEL];   // 16 MB  attn output
__device__ int   g_mask_is_i32;

// ---------------- mask dtype detector ----------------
// bool mask may arrive as 1-byte or int32. Read first 16384 bytes (safe either
// way); if every int32 word is 0/1 it is int32-encoded, else byte-encoded.
__global__ void detect_mask_kernel(const unsigned int* __restrict__ w) {
    __shared__ int bad;
    if (threadIdx.x == 0) bad = 0;
    __syncthreads();
    for (int i = threadIdx.x; i < 4096; i += 256)
        if (w[i] > 1u) bad = 1;
    __syncthreads();
    if (threadIdx.x == 0) g_mask_is_i32 = !bad;
}

// ---------------- classic 128x128x8 fp32 GEMM ----------------
// C[M,N] = alpha * A[M,K] @ B[K,N] (+bias). Optional column split at `splitN`:
// cols [0,splitN) -> C0 (ld=splitN), cols [splitN,N) -> C1 (ld=N-splitN).
__global__ __launch_bounds__(256) void sgemm128(
    const float* __restrict__ A, const float* __restrict__ B,
    float* __restrict__ C0, float* __restrict__ C1,
    int M, int N, int K, float alpha, const float* __restrict__ bias, int splitN)
{
    __shared__ float As[8][128];
    __shared__ float Bs[8][128];

    const int tid = threadIdx.x;
    const int bm = blockIdx.y * 128;
    const int bn = blockIdx.x * 128;

    const int a_row = tid >> 1;          // 0..127
    const int a_col = (tid & 1) << 2;    // 0 or 4
    const int b_row = tid >> 5;          // 0..7
    const int b_col = (tid & 31) << 2;   // 0..124

    const int tx = tid & 15;
    const int ty = tid >> 4;

    float acc[8][8];
#pragma unroll
    for (int i = 0; i < 8; i++)
#pragma unroll
        for (int j = 0; j < 8; j++) acc[i][j] = 0.0f;

    const float* Ap = A + (size_t)(bm + a_row) * K + a_col;
    const float* Bp = B + (size_t)b_row * N + bn + b_col;

    for (int k0 = 0; k0 < K; k0 += 8) {
        float4 av = *(const float4*)(Ap + k0);
        float4 bv = *(const float4*)(Bp + (size_t)k0 * N);
        __syncthreads();
        As[a_col + 0][a_row] = av.x;
        As[a_col + 1][a_row] = av.y;
        As[a_col + 2][a_row] = av.z;
        As[a_col + 3][a_row] = av.w;
        *(float4*)&Bs[b_row][b_col] = bv;
        __syncthreads();
#pragma unroll
        for (int kk = 0; kk < 8; kk++) {
            float af[8], bf[8];
            *(float4*)&af[0] = *(const float4*)&As[kk][ty * 4];
            *(float4*)&af[4] = *(const float4*)&As[kk][64 + ty * 4];
            *(float4*)&bf[0] = *(const float4*)&Bs[kk][tx * 4];
            *(float4*)&bf[4] = *(const float4*)&Bs[kk][64 + tx * 4];
#pragma unroll
            for (int i = 0; i < 8; i++)
#pragma unroll
                for (int j = 0; j < 8; j++)
                    acc[i][j] += af[i] * bf[j];
        }
    }

#pragma unroll
    for (int ih = 0; ih < 2; ih++)
#pragma unroll
        for (int ii = 0; ii < 4; ii++) {
            const int row = bm + ih * 64 + ty * 4 + ii;
#pragma unroll
            for (int jh = 0; jh < 2; jh++) {
                const int col = bn + jh * 64 + tx * 4;
                float4 v;
                v.x = alpha * acc[ih * 4 + ii][jh * 4 + 0];
                v.y = alpha * acc[ih * 4 + ii][jh * 4 + 1];
                v.z = alpha * acc[ih * 4 + ii][jh * 4 + 2];
                v.w = alpha * acc[ih * 4 + ii][jh * 4 + 3];
                if (bias) {
                    v.x += bias[col + 0]; v.y += bias[col + 1];
                    v.z += bias[col + 2]; v.w += bias[col + 3];
                }
                if (splitN && col >= splitN) {
                    const int ld = N - splitN;
                    *(float4*)(C1 + (size_t)row * ld + (col - splitN)) = v;
                } else {
                    const int ld = splitN ? splitN : N;
                    *(float4*)(C0 + (size_t)row * ld + col) = v;
                }
            }
        }
}

// ---------------- flash attention (64 q-rows x head x batch per CTA) --------
#define SP 68                           // smem pitch (floats)
#define ATT_SMEM (3 * 64 * SP * 4)      // Qs + Kt/Ps + Vs = 52224 B

__global__ __launch_bounds__(256) void attn_kernel(
    const float* __restrict__ qp, const float* __restrict__ kmat,
    const float* __restrict__ vmat, const void* __restrict__ maskp,
    float* __restrict__ xout)
{
    extern __shared__ float sm[];
    float* Qs  = sm;                // [64][SP], q-major
    float* KPs = sm + 64 * SP;      // K tile d-major, then P tile q-major
    float* Vs  = sm + 2 * 64 * SP;  // [64][SP], k-major

    const int tid = threadIdx.x;
    const int tx = tid & 15;
    const int ty = tid >> 4;
    const int q0 = blockIdx.x * 64;
    const int h  = blockIdx.y;
    const int b  = blockIdx.z;

    const float* qbase = qp   + ((size_t)b * NQ ) * D_MODEL + h * HDIM;
    const float* kbase = kmat + ((size_t)b * NKV) * D_MODEL + h * HDIM;
    const float* vbase = vmat + ((size_t)b * NKV) * D_MODEL + h * HDIM;
    const int mi32 = g_mask_is_i32;
    const unsigned char* m8  = (const unsigned char*)maskp + (size_t)b * NKV;
    const int*           m32 = (const int*)maskp           + (size_t)b * NKV;

    // load Q tile [64 x 64]
    {
        const int r = tid >> 2;
        const int c = (tid & 3) * 16;
        const float* src = qbase + (size_t)(q0 + r) * D_MODEL + c;
        float* dst = &Qs[r * SP + c];
#pragma unroll
        for (int i = 0; i < 4; i++)
            *(float4*)(dst + 4 * i) = *(const float4*)(src + 4 * i);
    }

    float m_run[4], l_run[4], o[4][4];
#pragma unroll
    for (int i = 0; i < 4; i++) {
        m_run[i] = -1e30f; l_run[i] = 0.0f;
#pragma unroll
        for (int j = 0; j < 4; j++) o[i][j] = 0.0f;
    }

    for (int k0 = 0; k0 < NKV; k0 += 64) {
        __syncthreads();  // previous PV reads done; Q store ordered by next bar
        // load K tile transposed (d-major) + V tile (k-major)
        {
            const int k = tid & 63;
            const int c = (tid >> 6) * 16;
            const float* ksrc = kbase + (size_t)(k0 + k) * D_MODEL + c;
#pragma unroll
            for (int i = 0; i < 16; i++)
                KPs[(c + i) * SP + k] = ksrc[i];
            const int r2 = tid >> 2;
            const int c2 = (tid & 3) * 16;
            const float* vsrc = vbase + (size_t)(k0 + r2) * D_MODEL + c2;
            float* vdst = &Vs[r2 * SP + c2];
#pragma unroll
            for (int i = 0; i < 4; i++)
                *(float4*)(vdst + 4 * i) = *(const float4*)(vsrc + 4 * i);
        }
        __syncthreads();

        // S = Q K^T for this 64x64 tile (thread owns 4q x 4k)
        float s[4][4];
#pragma unroll
        for (int i = 0; i < 4; i++)
#pragma unroll
            for (int j = 0; j < 4; j++) s[i][j] = 0.0f;

        for (int d = 0; d < 64; d++) {
            const float4 kf = *(const float4*)&KPs[d * SP + tx * 4];
#pragma unroll
            for (int i = 0; i < 4; i++) {
                const float qv = Qs[(ty * 4 + i) * SP + d];
                s[i][0] += qv * kf.x; s[i][1] += qv * kf.y;
                s[i][2] += qv * kf.z; s[i][3] += qv * kf.w;
            }
        }

        // apply padding mask
#pragma unroll
        for (int j = 0; j < 4; j++) {
            const int kk = k0 + tx * 4 + j;
            const bool masked = mi32 ? (m32[kk] != 0) : (m8[kk] != 0);
            if (masked) {
#pragma unroll
                for (int i = 0; i < 4; i++) s[i][j] = -1e30f;
            }
        }

        // online softmax update
        float p[4][4];
#pragma unroll
        for (int i = 0; i < 4; i++) {
            float rm = fmaxf(fmaxf(s[i][0], s[i][1]), fmaxf(s[i][2], s[i][3]));
#pragma unroll
            for (int off = 8; off >= 1; off >>= 1)
                rm = fmaxf(rm, __shfl_xor_sync(0xffffffffu, rm, off));
            const float mnew = fmaxf(m_run[i], rm);
            const float scale = __expf(m_run[i] - mnew);
            float rs = 0.0f;
#pragma unroll
            for (int j = 0; j < 4; j++) {
                p[i][j] = __expf(s[i][j] - mnew);
                rs += p[i][j];
            }
#pragma unroll
            for (int off = 8; off >= 1; off >>= 1)
                rs += __shfl_xor_sync(0xffffffffu, rs, off);
            l_run[i] = l_run[i] * scale + rs;
            m_run[i] = mnew;
#pragma unroll
            for (int j = 0; j < 4; j++) o[i][j] *= scale;
        }

        __syncthreads();  // all K-tile reads complete before P overwrites KPs
#pragma unroll
        for (int i = 0; i < 4; i++)
#pragma unroll
            for (int j = 0; j < 4; j++)
                KPs[(ty * 4 + i) * SP + tx * 4 + j] = p[i][j];
        __syncthreads();

        // O += P V (thread owns 4q x 4 output dims)
        for (int kk = 0; kk < 64; kk++) {
            const float4 vv = *(const float4*)&Vs[kk * SP + tx * 4];
#pragma unroll
            for (int i = 0; i < 4; i++) {
                const float pv = KPs[(ty * 4 + i) * SP + kk];
                o[i][0] += pv * vv.x; o[i][1] += pv * vv.y;
                o[i][2] += pv * vv.z; o[i][3] += pv * vv.w;
            }
        }
    }

#pragma unroll
    for (int i = 0; i < 4; i++) {
        const float inv = 1.0f / l_run[i];
        float4 r;
        r.x = o[i][0] * inv; r.y = o[i][1] * inv;
        r.z = o[i][2] * inv; r.w = o[i][3] * inv;
        const int row = q0 + ty * 4 + i;
        *(float4*)(xout + ((size_t)b * NQ + row) * D_MODEL + h * HDIM + tx * 4) = r;
    }
}

// ---------------- launch ----------------
extern "C" void kernel_launch(void* const* d_in, const int* in_sizes, int n_in,
                              void* d_out, int out_size) {
    const float* q     = (const float*)d_in[0];
    const float* kv    = (const float*)d_in[1];
    const void*  mask  = d_in[2];
    const float* Wq    = (const float*)d_in[3];
    const float* Wkv   = (const float*)d_in[4];
    const float* Wproj = (const float*)d_in[5];
    const float* bproj = (const float*)d_in[6];
    float* out = (float*)d_out;

    float *qp, *kmat, *vmat, *xbuf;
    cudaGetSymbolAddress((void**)&qp,   g_qp);
    cudaGetSymbolAddress((void**)&kmat, g_k);
    cudaGetSymbolAddress((void**)&vmat, g_v);
    cudaGetSymbolAddress((void**)&xbuf, g_x);

    cudaFuncSetAttribute(attn_kernel,
                         cudaFuncAttributeMaxDynamicSharedMemorySize, ATT_SMEM);

    detect_mask_kernel<<<1, 256>>>((const unsigned int*)mask);

    // qp = 0.125 * (q @ Wq)
    sgemm128<<<dim3(D_MODEL / 128, (BATCH * NQ) / 128), 256>>>(
        q, Wq, qp, nullptr, BATCH * NQ, D_MODEL, D_MODEL, 0.125f, nullptr, 0);

    // kvp = kv @ Wkv, split into k / v
    sgemm128<<<dim3((2 * D_MODEL) / 128, (BATCH * NKV) / 128), 256>>>(
        kv, Wkv, kmat, vmat, BATCH * NKV, 2 * D_MODEL, D_MODEL, 1.0f, nullptr,
        D_MODEL);

    // attention
    attn_kernel<<<dim3(NQ / 64, NHEADS, BATCH), 256, ATT_SMEM>>>(
        qp, kmat, vmat, mask, xbuf);

    // out = x @ Wproj + bproj
    sgemm128<<<dim3(D_MODEL / 128, (BATCH * NQ) / 128), 256>>>(
        xbuf, Wproj, out, nullptr, BATCH * NQ, D_MODEL, D_MODEL, 1.0f, bproj, 0);
}

// round 3
// speedup vs baseline: 1.3408x; 1.3408x over previous
#include <cuda_runtime.h>
#include <cstdint>

#define D_MODEL 1024
#define NQ      1024
#define NKV     4096
#define BATCH   4
#define NHEADS  16
#define HDIM    64

// ---------------- scratch (device globals: allocation-free) ----------------
__device__ float g_qp[(size_t)BATCH * NQ  * D_MODEL];   // 16 MB
__device__ float g_k [(size_t)BATCH * NKV * D_MODEL];   // 64 MB
__device__ float g_v [(size_t)BATCH * NKV * D_MODEL];   // 64 MB
__device__ float g_x [(size_t)BATCH * NQ  * D_MODEL];   // 16 MB
__device__ int   g_mask_is_i32;

// ---------------- helpers ----------------
__device__ __forceinline__ float f2tf32(float x) {
    float y;
    asm("cvt.rna.tf32.f32 %0, %1;" : "=f"(y) : "f"(x));
    return y;
}
__device__ __forceinline__ void mma_tf32(float* c, const uint32_t* a,
                                         const uint32_t* b) {
    asm volatile(
        "mma.sync.aligned.m16n8k8.row.col.f32.tf32.tf32.f32 "
        "{%0,%1,%2,%3}, {%4,%5,%6,%7}, {%8,%9}, {%0,%1,%2,%3};"
        : "+f"(c[0]), "+f"(c[1]), "+f"(c[2]), "+f"(c[3])
        : "r"(a[0]), "r"(a[1]), "r"(a[2]), "r"(a[3]), "r"(b[0]), "r"(b[1]));
}

// ---------------- mask dtype detector ----------------
__global__ void detect_mask_kernel(const unsigned int* __restrict__ w) {
    __shared__ int bad;
    if (threadIdx.x == 0) bad = 0;
    __syncthreads();
    for (int i = threadIdx.x; i < 4096; i += 256)
        if (w[i] > 1u) bad = 1;
    __syncthreads();
    if (threadIdx.x == 0) g_mask_is_i32 = !bad;
}

// ---------------- tf32 mma.sync GEMM: 128x128 tile, K-chunk 32 -------------
// C[M,N] = alpha * A[M,K] @ B[K,N] (+bias). Column split at splitN (0 = off).
#define LDA 36
#define LDB 132

__global__ __launch_bounds__(256, 2) void sgemm_mma(
    const float* __restrict__ A, const float* __restrict__ B,
    float* __restrict__ C0, float* __restrict__ C1,
    int M, int N, int K, float alpha, const float* __restrict__ bias, int splitN)
{
    __shared__ float As[128][LDA];   // [m][k], padded
    __shared__ float Bs[32][LDB];    // [k][n], padded

    const int tid = threadIdx.x;
    const int w   = tid >> 5;
    const int lane = tid & 31;
    const int g = lane >> 2;          // groupID 0..7
    const int t = lane & 3;           // threadID_in_group 0..3
    const int warpM = w >> 2;         // 0..1
    const int warpN = w & 3;          // 0..3
    const int bm = blockIdx.y * 128;
    const int bn = blockIdx.x * 128;

    const int r8 = tid >> 3;          // 0..31
    const int f8 = tid & 7;           // 0..7

    float acc[4][4][4];
#pragma unroll
    for (int mt = 0; mt < 4; mt++)
#pragma unroll
        for (int nt = 0; nt < 4; nt++)
#pragma unroll
            for (int i = 0; i < 4; i++) acc[mt][nt][i] = 0.0f;

    for (int k0 = 0; k0 < K; k0 += 32) {
        // prefetch chunk into registers (overlaps previous chunk's MMAs)
        float4 av[4], bv[4];
#pragma unroll
        for (int p = 0; p < 4; p++)
            av[p] = *(const float4*)(A + (size_t)(bm + p * 32 + r8) * K + k0 + f8 * 4);
#pragma unroll
        for (int j = 0; j < 4; j++)
            bv[j] = *(const float4*)(B + (size_t)(k0 + r8) * N + bn + (f8 + j * 8) * 4);

        __syncthreads();
#pragma unroll
        for (int p = 0; p < 4; p++) {
            float4 v = av[p];
            v.x = f2tf32(v.x); v.y = f2tf32(v.y);
            v.z = f2tf32(v.z); v.w = f2tf32(v.w);
            *(float4*)&As[p * 32 + r8][f8 * 4] = v;
        }
#pragma unroll
        for (int j = 0; j < 4; j++) {
            float4 v = bv[j];
            v.x = f2tf32(v.x); v.y = f2tf32(v.y);
            v.z = f2tf32(v.z); v.w = f2tf32(v.w);
            *(float4*)&Bs[r8][(f8 + j * 8) * 4] = v;
        }
        __syncthreads();

#pragma unroll
        for (int ks = 0; ks < 4; ks++) {
            const int kb = ks * 8;
            uint32_t af[4][4];
#pragma unroll
            for (int mt = 0; mt < 4; mt++) {
                const int row = warpM * 64 + mt * 16 + g;
                af[mt][0] = __float_as_uint(As[row    ][kb + t    ]);
                af[mt][1] = __float_as_uint(As[row + 8][kb + t    ]);
                af[mt][2] = __float_as_uint(As[row    ][kb + t + 4]);
                af[mt][3] = __float_as_uint(As[row + 8][kb + t + 4]);
            }
            uint32_t bf[4][2];
#pragma unroll
            for (int nt = 0; nt < 4; nt++) {
                const int col = warpN * 32 + nt * 8 + g;
                bf[nt][0] = __float_as_uint(Bs[kb + t    ][col]);
                bf[nt][1] = __float_as_uint(Bs[kb + t + 4][col]);
            }
#pragma unroll
            for (int mt = 0; mt < 4; mt++)
#pragma unroll
                for (int nt = 0; nt < 4; nt++)
                    mma_tf32(acc[mt][nt], af[mt], bf[nt]);
        }
    }

    // epilogue: c0 (row g, col 2t), c1 (col 2t+1), c2/c3 (row g+8)
#pragma unroll
    for (int mt = 0; mt < 4; mt++) {
#pragma unroll
        for (int nt = 0; nt < 4; nt++) {
            const int row0 = bm + warpM * 64 + mt * 16 + g;
            const int col  = bn + warpN * 32 + nt * 8 + 2 * t;
            float2 v0, v1;
            v0.x = alpha * acc[mt][nt][0];
            v0.y = alpha * acc[mt][nt][1];
            v1.x = alpha * acc[mt][nt][2];
            v1.y = alpha * acc[mt][nt][3];
            if (bias) {
                const float bx = bias[col], by = bias[col + 1];
                v0.x += bx; v0.y += by;
                v1.x += bx; v1.y += by;
            }
            float* dst;
            int ld;
            int c = col;
            if (splitN && col >= splitN) {
                ld = N - splitN; c = col - splitN; dst = C1;
            } else {
                ld = splitN ? splitN : N; dst = C0;
            }
            *(float2*)(dst + (size_t)row0 * ld + c)       = v0;
            *(float2*)(dst + (size_t)(row0 + 8) * ld + c) = v1;
        }
    }
}

// ---------------- flash attention (unchanged, verified) ----------------
#define SP 68
#define ATT_SMEM (3 * 64 * SP * 4)

__global__ __launch_bounds__(256) void attn_kernel(
    const float* __restrict__ qp, const float* __restrict__ kmat,
    const float* __restrict__ vmat, const void* __restrict__ maskp,
    float* __restrict__ xout)
{
    extern __shared__ float smf[];
    float* Qs  = smf;
    float* KPs = smf + 64 * SP;
    float* Vs  = smf + 2 * 64 * SP;

    const int tid = threadIdx.x;
    const int tx = tid & 15;
    const int ty = tid >> 4;
    const int q0 = blockIdx.x * 64;
    const int h  = blockIdx.y;
    const int b  = blockIdx.z;

    const float* qbase = qp   + ((size_t)b * NQ ) * D_MODEL + h * HDIM;
    const float* kbase = kmat + ((size_t)b * NKV) * D_MODEL + h * HDIM;
    const float* vbase = vmat + ((size_t)b * NKV) * D_MODEL + h * HDIM;
    const int mi32 = g_mask_is_i32;
    const unsigned char* m8  = (const unsigned char*)maskp + (size_t)b * NKV;
    const int*           m32 = (const int*)maskp           + (size_t)b * NKV;

    {
        const int r = tid >> 2;
        const int c = (tid & 3) * 16;
        const float* src = qbase + (size_t)(q0 + r) * D_MODEL + c;
        float* dst = &Qs[r * SP + c];
#pragma unroll
        for (int i = 0; i < 4; i++)
            *(float4*)(dst + 4 * i) = *(const float4*)(src + 4 * i);
    }

    float m_run[4], l_run[4], o[4][4];
#pragma unroll
    for (int i = 0; i < 4; i++) {
        m_run[i] = -1e30f; l_run[i] = 0.0f;
#pragma unroll
        for (int j = 0; j < 4; j++) o[i][j] = 0.0f;
    }

    for (int k0 = 0; k0 < NKV; k0 += 64) {
        __syncthreads();
        {
            const int k = tid & 63;
            const int c = (tid >> 6) * 16;
            const float* ksrc = kbase + (size_t)(k0 + k) * D_MODEL + c;
#pragma unroll
            for (int i = 0; i < 16; i++)
                KPs[(c + i) * SP + k] = ksrc[i];
            const int r2 = tid >> 2;
            const int c2 = (tid & 3) * 16;
            const float* vsrc = vbase + (size_t)(k0 + r2) * D_MODEL + c2;
            float* vdst = &Vs[r2 * SP + c2];
#pragma unroll
            for (int i = 0; i < 4; i++)
                *(float4*)(vdst + 4 * i) = *(const float4*)(vsrc + 4 * i);
        }
        __syncthreads();

        float s[4][4];
#pragma unroll
        for (int i = 0; i < 4; i++)
#pragma unroll
            for (int j = 0; j < 4; j++) s[i][j] = 0.0f;

        for (int d = 0; d < 64; d++) {
            const float4 kf = *(const float4*)&KPs[d * SP + tx * 4];
#pragma unroll
            for (int i = 0; i < 4; i++) {
                const float qv = Qs[(ty * 4 + i) * SP + d];
                s[i][0] += qv * kf.x; s[i][1] += qv * kf.y;
                s[i][2] += qv * kf.z; s[i][3] += qv * kf.w;
            }
        }

#pragma unroll
        for (int j = 0; j < 4; j++) {
            const int kk = k0 + tx * 4 + j;
            const bool masked = mi32 ? (m32[kk] != 0) : (m8[kk] != 0);
            if (masked) {
#pragma unroll
                for (int i = 0; i < 4; i++) s[i][j] = -1e30f;
            }
        }

        float p[4][4];
#pragma unroll
        for (int i = 0; i < 4; i++) {
            float rm = fmaxf(fmaxf(s[i][0], s[i][1]), fmaxf(s[i][2], s[i][3]));
#pragma unroll
            for (int off = 8; off >= 1; off >>= 1)
                rm = fmaxf(rm, __shfl_xor_sync(0xffffffffu, rm, off));
            const float mnew = fmaxf(m_run[i], rm);
            const float scale = __expf(m_run[i] - mnew);
            float rs = 0.0f;
#pragma unroll
            for (int j = 0; j < 4; j++) {
                p[i][j] = __expf(s[i][j] - mnew);
                rs += p[i][j];
            }
#pragma unroll
            for (int off = 8; off >= 1; off >>= 1)
                rs += __shfl_xor_sync(0xffffffffu, rs, off);
            l_run[i] = l_run[i] * scale + rs;
            m_run[i] = mnew;
#pragma unroll
            for (int j = 0; j < 4; j++) o[i][j] *= scale;
        }

        __syncthreads();
#pragma unroll
        for (int i = 0; i < 4; i++)
#pragma unroll
            for (int j = 0; j < 4; j++)
                KPs[(ty * 4 + i) * SP + tx * 4 + j] = p[i][j];
        __syncthreads();

        for (int kk = 0; kk < 64; kk++) {
            const float4 vv = *(const float4*)&Vs[kk * SP + tx * 4];
#pragma unroll
            for (int i = 0; i < 4; i++) {
                const float pv = KPs[(ty * 4 + i) * SP + kk];
                o[i][0] += pv * vv.x; o[i][1] += pv * vv.y;
                o[i][2] += pv * vv.z; o[i][3] += pv * vv.w;
            }
        }
    }

#pragma unroll
    for (int i = 0; i < 4; i++) {
        const float inv = 1.0f / l_run[i];
        float4 r;
        r.x = o[i][0] * inv; r.y = o[i][1] * inv;
        r.z = o[i][2] * inv; r.w = o[i][3] * inv;
        const int row = q0 + ty * 4 + i;
        *(float4*)(xout + ((size_t)b * NQ + row) * D_MODEL + h * HDIM + tx * 4) = r;
    }
}

// ---------------- launch ----------------
extern "C" void kernel_launch(void* const* d_in, const int* in_sizes, int n_in,
                              void* d_out, int out_size) {
    const float* q     = (const float*)d_in[0];
    const float* kv    = (const float*)d_in[1];
    const void*  mask  = d_in[2];
    const float* Wq    = (const float*)d_in[3];
    const float* Wkv   = (const float*)d_in[4];
    const float* Wproj = (const float*)d_in[5];
    const float* bproj = (const float*)d_in[6];
    float* out = (float*)d_out;

    float *qp, *kmat, *vmat, *xbuf;
    cudaGetSymbolAddress((void**)&qp,   g_qp);
    cudaGetSymbolAddress((void**)&kmat, g_k);
    cudaGetSymbolAddress((void**)&vmat, g_v);
    cudaGetSymbolAddress((void**)&xbuf, g_x);

    cudaFuncSetAttribute(attn_kernel,
                         cudaFuncAttributeMaxDynamicSharedMemorySize, ATT_SMEM);

    detect_mask_kernel<<<1, 256>>>((const unsigned int*)mask);

    // qp = 0.125 * (q @ Wq)
    sgemm_mma<<<dim3(D_MODEL / 128, (BATCH * NQ) / 128), 256>>>(
        q, Wq, qp, nullptr, BATCH * NQ, D_MODEL, D_MODEL, 0.125f, nullptr, 0);

    // kvp = kv @ Wkv, split into k / v
    sgemm_mma<<<dim3((2 * D_MODEL) / 128, (BATCH * NKV) / 128), 256>>>(
        kv, Wkv, kmat, vmat, BATCH * NKV, 2 * D_MODEL, D_MODEL, 1.0f, nullptr,
        D_MODEL);

    // attention (fp32)
    attn_kernel<<<dim3(NQ / 64, NHEADS, BATCH), 256, ATT_SMEM>>>(
        qp, kmat, vmat, mask, xbuf);

    // out = x @ Wproj + bproj
    sgemm_mma<<<dim3(D_MODEL / 128, (BATCH * NQ) / 128), 256>>>(
        xbuf, Wproj, out, nullptr, BATCH * NQ, D_MODEL, D_MODEL, 1.0f, bproj, 0);
}

// round 4
// speedup vs baseline: 2.4211x; 1.8058x over previous
#include <cuda_runtime.h>
#include <cstdint>

#define D_MODEL 1024
#define NQ      1024
#define NKV     4096
#define BATCH   4
#define NHEADS  16
#define HDIM    64

// ---------------- scratch (device globals: allocation-free) ----------------
__device__ float g_qp[(size_t)BATCH * NQ  * D_MODEL];   // 16 MB
__device__ float g_k [(size_t)BATCH * NKV * D_MODEL];   // 64 MB
__device__ float g_v [(size_t)BATCH * NKV * D_MODEL];   // 64 MB
__device__ float g_x [(size_t)BATCH * NQ  * D_MODEL];   // 16 MB
__device__ int   g_mask_is_i32;

// ---------------- helpers ----------------
__device__ __forceinline__ float f2tf32(float x) {
    float y;
    asm("cvt.rna.tf32.f32 %0, %1;" : "=f"(y) : "f"(x));
    return y;
}
__device__ __forceinline__ void mma_tf32(float* c, const uint32_t* a,
                                         const uint32_t* b) {
    asm volatile(
        "mma.sync.aligned.m16n8k8.row.col.f32.tf32.tf32.f32 "
        "{%0,%1,%2,%3}, {%4,%5,%6,%7}, {%8,%9}, {%0,%1,%2,%3};"
        : "+f"(c[0]), "+f"(c[1]), "+f"(c[2]), "+f"(c[3])
        : "r"(a[0]), "r"(a[1]), "r"(a[2]), "r"(a[3]), "r"(b[0]), "r"(b[1]));
}

// ---------------- mask dtype detector ----------------
__global__ void detect_mask_kernel(const unsigned int* __restrict__ w) {
    __shared__ int bad;
    if (threadIdx.x == 0) bad = 0;
    __syncthreads();
    for (int i = threadIdx.x; i < 4096; i += 256)
        if (w[i] > 1u) bad = 1;
    __syncthreads();
    if (threadIdx.x == 0) g_mask_is_i32 = !bad;
}

// ---------------- tf32 mma.sync GEMM: 128x128 tile, K-chunk 32 -------------
#define LDA 36
#define LDB 132

__global__ __launch_bounds__(256, 2) void sgemm_mma(
    const float* __restrict__ A, const float* __restrict__ B,
    float* __restrict__ C0, float* __restrict__ C1,
    int M, int N, int K, float alpha, const float* __restrict__ bias, int splitN)
{
    __shared__ float As[128][LDA];   // [m][k], padded
    __shared__ float Bs[32][LDB];    // [k][n], padded

    const int tid = threadIdx.x;
    const int w   = tid >> 5;
    const int lane = tid & 31;
    const int g = lane >> 2;
    const int t = lane & 3;
    const int warpM = w >> 2;
    const int warpN = w & 3;
    const int bm = blockIdx.y * 128;
    const int bn = blockIdx.x * 128;

    const int r8 = tid >> 3;
    const int f8 = tid & 7;

    float acc[4][4][4];
#pragma unroll
    for (int mt = 0; mt < 4; mt++)
#pragma unroll
        for (int nt = 0; nt < 4; nt++)
#pragma unroll
            for (int i = 0; i < 4; i++) acc[mt][nt][i] = 0.0f;

    for (int k0 = 0; k0 < K; k0 += 32) {
        float4 av[4], bv[4];
#pragma unroll
        for (int p = 0; p < 4; p++)
            av[p] = *(const float4*)(A + (size_t)(bm + p * 32 + r8) * K + k0 + f8 * 4);
#pragma unroll
        for (int j = 0; j < 4; j++)
            bv[j] = *(const float4*)(B + (size_t)(k0 + r8) * N + bn + (f8 + j * 8) * 4);

        __syncthreads();
#pragma unroll
        for (int p = 0; p < 4; p++) {
            float4 v = av[p];
            v.x = f2tf32(v.x); v.y = f2tf32(v.y);
            v.z = f2tf32(v.z); v.w = f2tf32(v.w);
            *(float4*)&As[p * 32 + r8][f8 * 4] = v;
        }
#pragma unroll
        for (int j = 0; j < 4; j++) {
            float4 v = bv[j];
            v.x = f2tf32(v.x); v.y = f2tf32(v.y);
            v.z = f2tf32(v.z); v.w = f2tf32(v.w);
            *(float4*)&Bs[r8][(f8 + j * 8) * 4] = v;
        }
        __syncthreads();

#pragma unroll
        for (int ks = 0; ks < 4; ks++) {
            const int kb = ks * 8;
            uint32_t af[4][4];
#pragma unroll
            for (int mt = 0; mt < 4; mt++) {
                const int row = warpM * 64 + mt * 16 + g;
                af[mt][0] = __float_as_uint(As[row    ][kb + t    ]);
                af[mt][1] = __float_as_uint(As[row + 8][kb + t    ]);
                af[mt][2] = __float_as_uint(As[row    ][kb + t + 4]);
                af[mt][3] = __float_as_uint(As[row + 8][kb + t + 4]);
            }
            uint32_t bf[4][2];
#pragma unroll
            for (int nt = 0; nt < 4; nt++) {
                const int col = warpN * 32 + nt * 8 + g;
                bf[nt][0] = __float_as_uint(Bs[kb + t    ][col]);
                bf[nt][1] = __float_as_uint(Bs[kb + t + 4][col]);
            }
#pragma unroll
            for (int mt = 0; mt < 4; mt++)
#pragma unroll
                for (int nt = 0; nt < 4; nt++)
                    mma_tf32(acc[mt][nt], af[mt], bf[nt]);
        }
    }

#pragma unroll
    for (int mt = 0; mt < 4; mt++) {
#pragma unroll
        for (int nt = 0; nt < 4; nt++) {
            const int row0 = bm + warpM * 64 + mt * 16 + g;
            const int col  = bn + warpN * 32 + nt * 8 + 2 * t;
            float2 v0, v1;
            v0.x = alpha * acc[mt][nt][0];
            v0.y = alpha * acc[mt][nt][1];
            v1.x = alpha * acc[mt][nt][2];
            v1.y = alpha * acc[mt][nt][3];
            if (bias) {
                const float bx = bias[col], by = bias[col + 1];
                v0.x += bx; v0.y += by;
                v1.x += bx; v1.y += by;
            }
            float* dst;
            int ld;
            int c = col;
            if (splitN && col >= splitN) {
                ld = N - splitN; c = col - splitN; dst = C1;
            } else {
                ld = splitN ? splitN : N; dst = C0;
            }
            *(float2*)(dst + (size_t)row0 * ld + c)       = v0;
            *(float2*)(dst + (size_t)(row0 + 8) * ld + c) = v1;
        }
    }
}

// ---------------- flash attention with tf32 mma.sync -----------------------
// CTA: 64 q-rows x 1 head x 1 batch; 4 warps, each owns 16 q-rows.
// KV tile 64. Q fragments persist in registers.
#define APITCH 68
#define ATT_SMEM ((3 * 64 * APITCH + 64) * 4)

__global__ __launch_bounds__(128, 3) void attn_mma(
    const float* __restrict__ qp, const float* __restrict__ kmat,
    const float* __restrict__ vmat, const void* __restrict__ maskp,
    float* __restrict__ xout)
{
    extern __shared__ float smf[];
    float* Ks   = smf;                       // [hd][kv] d-major
    float* Vs   = smf + 64 * APITCH;         // [kv][hd]
    float* Ps   = smf + 2 * 64 * APITCH;     // Q staging, then P tiles
    float* mskb = smf + 3 * 64 * APITCH;     // additive mask bias [64]

    const int tid = threadIdx.x;
    const int w = tid >> 5, lane = tid & 31;
    const int g = lane >> 2, t = lane & 3;
    const int q0 = blockIdx.x * 64;
    const int hh = blockIdx.y;
    const int b  = blockIdx.z;

    const float* qbase = qp   + ((size_t)b * NQ + q0) * D_MODEL + hh * HDIM;
    const float* kbase = kmat + (size_t)b * NKV * D_MODEL + hh * HDIM;
    const float* vbase = vmat + (size_t)b * NKV * D_MODEL + hh * HDIM;
    const int mi32 = g_mask_is_i32;
    const unsigned char* m8  = (const unsigned char*)maskp + (size_t)b * NKV;
    const int*           m32 = (const int*)maskp           + (size_t)b * NKV;

    // stage Q tile [64][64] into Ps (tf32-rounded)
    {
        const int r = tid >> 1, c0 = (tid & 1) * 32;
        const float* src = qbase + (size_t)r * D_MODEL + c0;
        float* dst = &Ps[r * APITCH + c0];
#pragma unroll
        for (int i = 0; i < 8; i++) {
            float4 v = *(const float4*)(src + 4 * i);
            v.x = f2tf32(v.x); v.y = f2tf32(v.y);
            v.z = f2tf32(v.z); v.w = f2tf32(v.w);
            *(float4*)(dst + 4 * i) = v;
        }
    }
    __syncthreads();

    // preload Q fragments (A operand, K=64 -> 8 k-steps)
    const int mrow = w * 16 + g;
    uint32_t aq[8][4];
#pragma unroll
    for (int ks = 0; ks < 8; ks++) {
        const int kb = ks * 8;
        aq[ks][0] = __float_as_uint(Ps[ mrow      * APITCH + kb + t    ]);
        aq[ks][1] = __float_as_uint(Ps[(mrow + 8) * APITCH + kb + t    ]);
        aq[ks][2] = __float_as_uint(Ps[ mrow      * APITCH + kb + t + 4]);
        aq[ks][3] = __float_as_uint(Ps[(mrow + 8) * APITCH + kb + t + 4]);
    }

    float m_run[2] = {-1e30f, -1e30f};
    float l_run[2] = {0.0f, 0.0f};
    float o[8][4];
#pragma unroll
    for (int j = 0; j < 8; j++)
#pragma unroll
        for (int i = 0; i < 4; i++) o[j][i] = 0.0f;

    for (int k0 = 0; k0 < NKV; k0 += 64) {
        __syncthreads();  // prior tile fully consumed (and Q frags loaded)

        // K tile transposed: Ks[d][kv] (tf32)
        {
            const int k = tid & 63;
            const int c0 = (tid >> 6) * 32;
            const float* src = kbase + (size_t)(k0 + k) * D_MODEL + c0;
#pragma unroll
            for (int i = 0; i < 8; i++) {
                float4 v = *(const float4*)(src + 4 * i);
                Ks[(c0 + 4 * i + 0) * APITCH + k] = f2tf32(v.x);
                Ks[(c0 + 4 * i + 1) * APITCH + k] = f2tf32(v.y);
                Ks[(c0 + 4 * i + 2) * APITCH + k] = f2tf32(v.z);
                Ks[(c0 + 4 * i + 3) * APITCH + k] = f2tf32(v.w);
            }
        }
        // V tile: Vs[kv][hd] (tf32)
        {
            const int r = tid >> 1, c0 = (tid & 1) * 32;
            const float* src = vbase + (size_t)(k0 + r) * D_MODEL + c0;
            float* dst = &Vs[r * APITCH + c0];
#pragma unroll
            for (int i = 0; i < 8; i++) {
                float4 v = *(const float4*)(src + 4 * i);
                v.x = f2tf32(v.x); v.y = f2tf32(v.y);
                v.z = f2tf32(v.z); v.w = f2tf32(v.w);
                *(float4*)(dst + 4 * i) = v;
            }
        }
        // mask bias
        if (tid < 64) {
            const int kk = k0 + tid;
            const bool masked = mi32 ? (m32[kk] != 0) : (m8[kk] != 0);
            mskb[tid] = masked ? -1e30f : 0.0f;
        }
        __syncthreads();

        // S = Q K^T  (8 n-tiles of n8 over kv)
        float s[8][4];
#pragma unroll
        for (int j = 0; j < 8; j++)
#pragma unroll
            for (int i = 0; i < 4; i++) s[j][i] = 0.0f;

#pragma unroll
        for (int ks = 0; ks < 8; ks++) {
            const int kb = ks * 8;
            uint32_t bf[8][2];
#pragma unroll
            for (int j = 0; j < 8; j++) {
                bf[j][0] = __float_as_uint(Ks[(kb + t    ) * APITCH + j * 8 + g]);
                bf[j][1] = __float_as_uint(Ks[(kb + t + 4) * APITCH + j * 8 + g]);
            }
#pragma unroll
            for (int j = 0; j < 8; j++)
                mma_tf32(s[j], aq[ks], bf[j]);
        }

        // mask bias + online softmax (rows g and g+8)
        float rm0 = -1e30f, rm1 = -1e30f;
#pragma unroll
        for (int j = 0; j < 8; j++) {
            const float b0 = mskb[j * 8 + 2 * t];
            const float b1 = mskb[j * 8 + 2 * t + 1];
            s[j][0] += b0; s[j][1] += b1;
            s[j][2] += b0; s[j][3] += b1;
            rm0 = fmaxf(rm0, fmaxf(s[j][0], s[j][1]));
            rm1 = fmaxf(rm1, fmaxf(s[j][2], s[j][3]));
        }
        rm0 = fmaxf(rm0, __shfl_xor_sync(0xffffffffu, rm0, 1));
        rm0 = fmaxf(rm0, __shfl_xor_sync(0xffffffffu, rm0, 2));
        rm1 = fmaxf(rm1, __shfl_xor_sync(0xffffffffu, rm1, 1));
        rm1 = fmaxf(rm1, __shfl_xor_sync(0xffffffffu, rm1, 2));

        const float mn0 = fmaxf(m_run[0], rm0);
        const float mn1 = fmaxf(m_run[1], rm1);
        const float sc0 = __expf(m_run[0] - mn0);
        const float sc1 = __expf(m_run[1] - mn1);
        float rs0 = 0.0f, rs1 = 0.0f;
#pragma unroll
        for (int j = 0; j < 8; j++) {
            s[j][0] = __expf(s[j][0] - mn0); rs0 += s[j][0];
            s[j][1] = __expf(s[j][1] - mn0); rs0 += s[j][1];
            s[j][2] = __expf(s[j][2] - mn1); rs1 += s[j][2];
            s[j][3] = __expf(s[j][3] - mn1); rs1 += s[j][3];
        }
        rs0 += __shfl_xor_sync(0xffffffffu, rs0, 1);
        rs0 += __shfl_xor_sync(0xffffffffu, rs0, 2);
        rs1 += __shfl_xor_sync(0xffffffffu, rs1, 1);
        rs1 += __shfl_xor_sync(0xffffffffu, rs1, 2);
        l_run[0] = l_run[0] * sc0 + rs0;
        l_run[1] = l_run[1] * sc1 + rs1;
        m_run[0] = mn0;
        m_run[1] = mn1;
#pragma unroll
        for (int j = 0; j < 8; j++) {
            o[j][0] *= sc0; o[j][1] *= sc0;
            o[j][2] *= sc1; o[j][3] *= sc1;
        }

        // write P (own warp rows only) then consume as A operand
#pragma unroll
        for (int j = 0; j < 8; j++) {
            float2 p0, p1;
            p0.x = f2tf32(s[j][0]); p0.y = f2tf32(s[j][1]);
            p1.x = f2tf32(s[j][2]); p1.y = f2tf32(s[j][3]);
            *(float2*)&Ps[ mrow      * APITCH + j * 8 + 2 * t] = p0;
            *(float2*)&Ps[(mrow + 8) * APITCH + j * 8 + 2 * t] = p1;
        }
        __syncwarp();

        // O += P V  (K dim = 64 kv positions -> 8 k-steps)
#pragma unroll
        for (int ks = 0; ks < 8; ks++) {
            const int kb = ks * 8;
            uint32_t ap[4];
            ap[0] = __float_as_uint(Ps[ mrow      * APITCH + kb + t    ]);
            ap[1] = __float_as_uint(Ps[(mrow + 8) * APITCH + kb + t    ]);
            ap[2] = __float_as_uint(Ps[ mrow      * APITCH + kb + t + 4]);
            ap[3] = __float_as_uint(Ps[(mrow + 8) * APITCH + kb + t + 4]);
            uint32_t bv[8][2];
#pragma unroll
            for (int j = 0; j < 8; j++) {
                bv[j][0] = __float_as_uint(Vs[(kb + t    ) * APITCH + j * 8 + g]);
                bv[j][1] = __float_as_uint(Vs[(kb + t + 4) * APITCH + j * 8 + g]);
            }
#pragma unroll
            for (int j = 0; j < 8; j++)
                mma_tf32(o[j], ap, bv[j]);
        }
        __syncwarp();  // P reads done before next tile's (warp-local) reuse
    }

    // write output
    const float inv0 = 1.0f / l_run[0];
    const float inv1 = 1.0f / l_run[1];
    float* orow0 = xout + ((size_t)b * NQ + q0 + mrow    ) * D_MODEL + hh * HDIM;
    float* orow1 = xout + ((size_t)b * NQ + q0 + mrow + 8) * D_MODEL + hh * HDIM;
#pragma unroll
    for (int j = 0; j < 8; j++) {
        float2 v0, v1;
        v0.x = o[j][0] * inv0; v0.y = o[j][1] * inv0;
        v1.x = o[j][2] * inv1; v1.y = o[j][3] * inv1;
        *(float2*)(orow0 + j * 8 + 2 * t) = v0;
        *(float2*)(orow1 + j * 8 + 2 * t) = v1;
    }
}

// ---------------- launch ----------------
extern "C" void kernel_launch(void* const* d_in, const int* in_sizes, int n_in,
                              void* d_out, int out_size) {
    const float* q     = (const float*)d_in[0];
    const float* kv    = (const float*)d_in[1];
    const void*  mask  = d_in[2];
    const float* Wq    = (const float*)d_in[3];
    const float* Wkv   = (const float*)d_in[4];
    const float* Wproj = (const float*)d_in[5];
    const float* bproj = (const float*)d_in[6];
    float* out = (float*)d_out;

    float *qp, *kmat, *vmat, *xbuf;
    cudaGetSymbolAddress((void**)&qp,   g_qp);
    cudaGetSymbolAddress((void**)&kmat, g_k);
    cudaGetSymbolAddress((void**)&vmat, g_v);
    cudaGetSymbolAddress((void**)&xbuf, g_x);

    cudaFuncSetAttribute(attn_mma,
                         cudaFuncAttributeMaxDynamicSharedMemorySize, ATT_SMEM);

    detect_mask_kernel<<<1, 256>>>((const unsigned int*)mask);

    // qp = 0.125 * (q @ Wq)
    sgemm_mma<<<dim3(D_MODEL / 128, (BATCH * NQ) / 128), 256>>>(
        q, Wq, qp, nullptr, BATCH * NQ, D_MODEL, D_MODEL, 0.125f, nullptr, 0);

    // kvp = kv @ Wkv, split into k / v
    sgemm_mma<<<dim3((2 * D_MODEL) / 128, (BATCH * NKV) / 128), 256>>>(
        kv, Wkv, kmat, vmat, BATCH * NKV, 2 * D_MODEL, D_MODEL, 1.0f, nullptr,
        D_MODEL);

    // attention (tf32 tensor cores)
    attn_mma<<<dim3(NQ / 64, NHEADS, BATCH), 128, ATT_SMEM>>>(
        qp, kmat, vmat, mask, xbuf);

    // out = x @ Wproj + bproj
    sgemm_mma<<<dim3(D_MODEL / 128, (BATCH * NQ) / 128), 256>>>(
        xbuf, Wproj, out, nullptr, BATCH * NQ, D_MODEL, D_MODEL, 1.0f, bproj, 0);
}

// round 5
// speedup vs baseline: 2.5323x; 1.0459x over previous
#include <cuda_runtime.h>
#include <cstdint>

#define D_MODEL 1024
#define NQ      1024
#define NKV     4096
#define BATCH   4
#define NHEADS  16
#define HDIM    64

// ---------------- scratch (device globals: allocation-free) ----------------
__device__ float g_qp[(size_t)BATCH * NQ  * D_MODEL];   // 16 MB
__device__ float g_k [(size_t)BATCH * NKV * D_MODEL];   // 64 MB
__device__ float g_v [(size_t)BATCH * NKV * D_MODEL];   // 64 MB
__device__ float g_x [(size_t)BATCH * NQ  * D_MODEL];   // 16 MB
__device__ int   g_mask_is_i32;

// ---------------- helpers ----------------
__device__ __forceinline__ float f2tf32(float x) {
    float y;
    asm("cvt.rna.tf32.f32 %0, %1;" : "=f"(y) : "f"(x));
    return y;
}
__device__ __forceinline__ void mma_tf32(float* c, const uint32_t* a,
                                         const uint32_t* b) {
    asm volatile(
        "mma.sync.aligned.m16n8k8.row.col.f32.tf32.tf32.f32 "
        "{%0,%1,%2,%3}, {%4,%5,%6,%7}, {%8,%9}, {%0,%1,%2,%3};"
        : "+f"(c[0]), "+f"(c[1]), "+f"(c[2]), "+f"(c[3])
        : "r"(a[0]), "r"(a[1]), "r"(a[2]), "r"(a[3]), "r"(b[0]), "r"(b[1]));
}
__device__ __forceinline__ uint32_t smem_u32(const void* p) {
    uint32_t a;
    asm("{ .reg .u64 t; cvta.to.shared.u64 t, %1; cvt.u32.u64 %0, t; }"
        : "=r"(a) : "l"(p));
    return a;
}
// ldmatrix x4 (b16 semantics; pure bit movement, works for tf32 fragments)
__device__ __forceinline__ void ldsm4(uint32_t* d, uint32_t addr) {
    asm volatile(
        "ldmatrix.sync.aligned.m8n8.x4.shared.b16 {%0,%1,%2,%3}, [%4];"
        : "=r"(d[0]), "=r"(d[1]), "=r"(d[2]), "=r"(d[3]) : "r"(addr));
}

// ---------------- mask dtype detector ----------------
__global__ void detect_mask_kernel(const unsigned int* __restrict__ w) {
    __shared__ int bad;
    if (threadIdx.x == 0) bad = 0;
    __syncthreads();
    for (int i = threadIdx.x; i < 4096; i += 256)
        if (w[i] > 1u) bad = 1;
    __syncthreads();
    if (threadIdx.x == 0) g_mask_is_i32 = !bad;
}

// ---------------- tf32 mma.sync GEMM: 128x128 tile, K-chunk 32 -------------
// A frags + B frags via ldmatrix. Bs stored N-major for direct B fragments.
#define LDA 36
#define LDBN 36

__global__ __launch_bounds__(256, 2) void sgemm_mma(
    const float* __restrict__ A, const float* __restrict__ B,
    float* __restrict__ C0, float* __restrict__ C1,
    int M, int N, int K, float alpha, const float* __restrict__ bias, int splitN)
{
    __shared__ __align__(16) float As[128][LDA];    // [m][k]
    __shared__ __align__(16) float Bsn[128][LDBN];  // [n][k]  (N-major!)

    const int tid = threadIdx.x;
    const int w   = tid >> 5;
    const int lane = tid & 31;
    const int warpM = w >> 2;
    const int warpN = w & 3;
    const int bm = blockIdx.y * 128;
    const int bn = blockIdx.x * 128;

    const int r8 = tid >> 3;
    const int f8 = tid & 7;

    const uint32_t sbA = smem_u32(As);
    const uint32_t sbB = smem_u32(Bsn);

    // per-lane ldmatrix byte-offsets (excluding kb)
    const int lr  = lane & 7;
    const int lhi = (lane >> 4) & 1;   // tile parity / row-half selector
    const int lhf = (lane >> 3) & 1;   // k-half selector
    uint32_t aoff[4], boff[2];
#pragma unroll
    for (int mt = 0; mt < 4; mt++)
        aoff[mt] = sbA + ((warpM * 64 + mt * 16 + (lane & 15)) * LDA +
                          4 * (lane >> 4)) * 4;
#pragma unroll
    for (int nt2 = 0; nt2 < 2; nt2++)
        boff[nt2] = sbB + ((warpN * 32 + (2 * nt2 + lhi) * 8 + lr) * LDBN +
                           4 * lhf) * 4;

    float acc[4][4][4];
#pragma unroll
    for (int mt = 0; mt < 4; mt++)
#pragma unroll
        for (int nt = 0; nt < 4; nt++)
#pragma unroll
            for (int i = 0; i < 4; i++) acc[mt][nt][i] = 0.0f;

    const int bn_n = tid & 127;        // B-load: n index (coalesced per warp)
    const int kq_b = tid >> 7;         // 0..1

    for (int k0 = 0; k0 < K; k0 += 32) {
        // prefetch A rows (float4) + B columns (scalar along k)
        float4 av[4];
#pragma unroll
        for (int p = 0; p < 4; p++)
            av[p] = *(const float4*)(A + (size_t)(bm + p * 32 + r8) * K + k0 + f8 * 4);
        float bld[4][4];
#pragma unroll
        for (int it = 0; it < 4; it++) {
            const int kk = (2 * it + kq_b) * 4;
            const float* Bp = B + (size_t)(k0 + kk) * N + bn + bn_n;
#pragma unroll
            for (int c = 0; c < 4; c++)
                bld[it][c] = Bp[(size_t)c * N];
        }

        __syncthreads();
#pragma unroll
        for (int p = 0; p < 4; p++) {
            float4 v = av[p];
            v.x = f2tf32(v.x); v.y = f2tf32(v.y);
            v.z = f2tf32(v.z); v.w = f2tf32(v.w);
            *(float4*)&As[p * 32 + r8][f8 * 4] = v;
        }
#pragma unroll
        for (int it = 0; it < 4; it++) {
            const int kk = (2 * it + kq_b) * 4;
            float4 v;
            v.x = f2tf32(bld[it][0]); v.y = f2tf32(bld[it][1]);
            v.z = f2tf32(bld[it][2]); v.w = f2tf32(bld[it][3]);
            *(float4*)&Bsn[bn_n][kk] = v;
        }
        __syncthreads();

#pragma unroll
        for (int ks = 0; ks < 4; ks++) {
            const int kb4 = ks * 8 * 4;   // kb in bytes
            uint32_t af[4][4];
#pragma unroll
            for (int mt = 0; mt < 4; mt++)
                ldsm4(af[mt], aoff[mt] + kb4);
#pragma unroll
            for (int nt2 = 0; nt2 < 2; nt2++) {
                uint32_t bf4[4];
                ldsm4(bf4, boff[nt2] + kb4);
#pragma unroll
                for (int mt = 0; mt < 4; mt++) {
                    mma_tf32(acc[mt][2 * nt2],     af[mt], &bf4[0]);
                    mma_tf32(acc[mt][2 * nt2 + 1], af[mt], &bf4[2]);
                }
            }
        }
    }

    const int g = lane >> 2;
    const int t = lane & 3;
#pragma unroll
    for (int mt = 0; mt < 4; mt++) {
#pragma unroll
        for (int nt = 0; nt < 4; nt++) {
            const int row0 = bm + warpM * 64 + mt * 16 + g;
            const int col  = bn + warpN * 32 + nt * 8 + 2 * t;
            float2 v0, v1;
            v0.x = alpha * acc[mt][nt][0];
            v0.y = alpha * acc[mt][nt][1];
            v1.x = alpha * acc[mt][nt][2];
            v1.y = alpha * acc[mt][nt][3];
            if (bias) {
                const float bx = bias[col], by = bias[col + 1];
                v0.x += bx; v0.y += by;
                v1.x += bx; v1.y += by;
            }
            float* dst;
            int ld;
            int c = col;
            if (splitN && col >= splitN) {
                ld = N - splitN; c = col - splitN; dst = C1;
            } else {
                ld = splitN ? splitN : N; dst = C0;
            }
            *(float2*)(dst + (size_t)row0 * ld + c)       = v0;
            *(float2*)(dst + (size_t)(row0 + 8) * ld + c) = v1;
        }
    }
}

// ---------------- flash attention: tf32 mma + ldmatrix ---------------------
// CTA: 64 q-rows x head x batch; 4 warps x 16 q-rows. KV tile 64.
// K stored kv-major (native) -> QK B-frags via ldmatrix.
// V stored d-major (transposed) -> PV B-frags via ldmatrix.
#define AP 68
#define ATT_SMEM ((3 * 64 * AP + 64) * 4)

__global__ __launch_bounds__(128, 3) void attn_mma(
    const float* __restrict__ qp, const float* __restrict__ kmat,
    const float* __restrict__ vmat, const void* __restrict__ maskp,
    float* __restrict__ xout)
{
    extern __shared__ float smf[];
    float* Kn   = smf;                  // [kv=64][AP] native
    float* Vt   = smf + 64 * AP;        // [d=64][AP] transposed
    float* Ps   = smf + 2 * 64 * AP;    // Q staging, then P [q=64][AP]
    float* mskb = smf + 3 * 64 * AP;    // additive mask bias [64]

    const int tid = threadIdx.x;
    const int w = tid >> 5, lane = tid & 31;
    const int g = lane >> 2, t = lane & 3;
    const int q0 = blockIdx.x * 64;
    const int hh = blockIdx.y;
    const int b  = blockIdx.z;

    const uint32_t sbK = smem_u32(Kn);
    const uint32_t sbV = smem_u32(Vt);
    const uint32_t sbP = smem_u32(Ps);

    const float* qbase = qp   + ((size_t)b * NQ + q0) * D_MODEL + hh * HDIM;
    const float* kbase = kmat + (size_t)b * NKV * D_MODEL + hh * HDIM;
    const float* vbase = vmat + (size_t)b * NKV * D_MODEL + hh * HDIM;
    const int mi32 = g_mask_is_i32;
    const unsigned char* m8  = (const unsigned char*)maskp + (size_t)b * NKV;
    const int*           m32 = (const int*)maskp           + (size_t)b * NKV;

    // per-lane ldmatrix byte offsets (excluding kb)
    const int lr  = lane & 7;
    const int lhi = (lane >> 4) & 1;
    const int lhf = (lane >> 3) & 1;
    uint32_t preB[4];
#pragma unroll
    for (int j2 = 0; j2 < 4; j2++)
        preB[j2] = (((2 * j2 + lhi) * 8 + lr) * AP + 4 * lhf) * 4;
    const uint32_t preA = ((w * 16 + (lane & 15)) * AP + 4 * (lane >> 4)) * 4;

    // stage Q tile (each warp stages its own 16 rows: tid>>1 in [w*16, w*16+16))
    {
        const int r = tid >> 1, c0 = (tid & 1) * 32;
        const float* src = qbase + (size_t)r * D_MODEL + c0;
        float* dst = &Ps[r * AP + c0];
#pragma unroll
        for (int i = 0; i < 8; i++) {
            float4 v = *(const float4*)(src + 4 * i);
            v.x = f2tf32(v.x); v.y = f2tf32(v.y);
            v.z = f2tf32(v.z); v.w = f2tf32(v.w);
            *(float4*)(dst + 4 * i) = v;
        }
    }
    __syncthreads();

    // preload Q fragments via ldmatrix (8 k-steps over d=64)
    const int mrow = w * 16 + g;
    uint32_t aq[8][4];
#pragma unroll
    for (int ks = 0; ks < 8; ks++)
        ldsm4(aq[ks], sbP + preA + ks * 32);

    float m_run[2] = {-1e30f, -1e30f};
    float l_run[2] = {0.0f, 0.0f};
    float o[8][4];
#pragma unroll
    for (int j = 0; j < 8; j++)
#pragma unroll
        for (int i = 0; i < 4; i++) o[j][i] = 0.0f;

    for (int k0 = 0; k0 < NKV; k0 += 64) {
        __syncthreads();  // prior tile fully consumed

        // K tile native [kv][d] (vectorized)
        {
            const int r = tid >> 1, c0 = (tid & 1) * 32;
            const float* src = kbase + (size_t)(k0 + r) * D_MODEL + c0;
            float* dst = &Kn[r * AP + c0];
#pragma unroll
            for (int i = 0; i < 8; i++) {
                float4 v = *(const float4*)(src + 4 * i);
                v.x = f2tf32(v.x); v.y = f2tf32(v.y);
                v.z = f2tf32(v.z); v.w = f2tf32(v.w);
                *(float4*)(dst + 4 * i) = v;
            }
        }
        // V tile transposed [d][kv] (scalar, conflict-free: lanes->consecutive kv)
        {
            const int k = tid & 63;
            const int c0 = (tid >> 6) * 32;
            const float* src = vbase + (size_t)(k0 + k) * D_MODEL + c0;
#pragma unroll
            for (int i = 0; i < 8; i++) {
                float4 v = *(const float4*)(src + 4 * i);
                Vt[(c0 + 4 * i + 0) * AP + k] = f2tf32(v.x);
                Vt[(c0 + 4 * i + 1) * AP + k] = f2tf32(v.y);
                Vt[(c0 + 4 * i + 2) * AP + k] = f2tf32(v.z);
                Vt[(c0 + 4 * i + 3) * AP + k] = f2tf32(v.w);
            }
        }
        // mask bias
        if (tid < 64) {
            const int kk = k0 + tid;
            const bool masked = mi32 ? (m32[kk] != 0) : (m8[kk] != 0);
            mskb[tid] = masked ? -1e30f : 0.0f;
        }
        __syncthreads();

        // S = Q K^T : per k-step, 4 LDSM.x4 give all 8 n-tiles' B frags
        float s[8][4];
#pragma unroll
        for (int j = 0; j < 8; j++)
#pragma unroll
            for (int i = 0; i < 4; i++) s[j][i] = 0.0f;

#pragma unroll
        for (int ks = 0; ks < 8; ks++) {
            const int kb4 = ks * 32;   // 8 floats in bytes
#pragma unroll
            for (int j2 = 0; j2 < 4; j2++) {
                uint32_t bf4[4];
                ldsm4(bf4, sbK + preB[j2] + kb4);
                mma_tf32(s[2 * j2],     aq[ks], &bf4[0]);
                mma_tf32(s[2 * j2 + 1], aq[ks], &bf4[2]);
            }
        }

        // mask bias + online softmax (rows g and g+8)
        float rm0 = -1e30f, rm1 = -1e30f;
#pragma unroll
        for (int j = 0; j < 8; j++) {
            const float b0 = mskb[j * 8 + 2 * t];
            const float b1 = mskb[j * 8 + 2 * t + 1];
            s[j][0] += b0; s[j][1] += b1;
            s[j][2] += b0; s[j][3] += b1;
            rm0 = fmaxf(rm0, fmaxf(s[j][0], s[j][1]));
            rm1 = fmaxf(rm1, fmaxf(s[j][2], s[j][3]));
        }
        rm0 = fmaxf(rm0, __shfl_xor_sync(0xffffffffu, rm0, 1));
        rm0 = fmaxf(rm0, __shfl_xor_sync(0xffffffffu, rm0, 2));
        rm1 = fmaxf(rm1, __shfl_xor_sync(0xffffffffu, rm1, 1));
        rm1 = fmaxf(rm1, __shfl_xor_sync(0xffffffffu, rm1, 2));

        const float mn0 = fmaxf(m_run[0], rm0);
        const float mn1 = fmaxf(m_run[1], rm1);
        const float sc0 = __expf(m_run[0] - mn0);
        const float sc1 = __expf(m_run[1] - mn1);
        float rs0 = 0.0f, rs1 = 0.0f;
#pragma unroll
        for (int j = 0; j < 8; j++) {
            s[j][0] = __expf(s[j][0] - mn0); rs0 += s[j][0];
            s[j][1] = __expf(s[j][1] - mn0); rs0 += s[j][1];
            s[j][2] = __expf(s[j][2] - mn1); rs1 += s[j][2];
            s[j][3] = __expf(s[j][3] - mn1); rs1 += s[j][3];
        }
        rs0 += __shfl_xor_sync(0xffffffffu, rs0, 1);
        rs0 += __shfl_xor_sync(0xffffffffu, rs0, 2);
        rs1 += __shfl_xor_sync(0xffffffffu, rs1, 1);
        rs1 += __shfl_xor_sync(0xffffffffu, rs1, 2);
        l_run[0] = l_run[0] * sc0 + rs0;
        l_run[1] = l_run[1] * sc1 + rs1;
        m_run[0] = mn0;
        m_run[1] = mn1;
#pragma unroll
        for (int j = 0; j < 8; j++) {
            o[j][0] *= sc0; o[j][1] *= sc0;
            o[j][2] *= sc1; o[j][3] *= sc1;
        }

        // write P (warp-private rows), consume via ldmatrix
#pragma unroll
        for (int j = 0; j < 8; j++) {
            float2 p0, p1;
            p0.x = f2tf32(s[j][0]); p0.y = f2tf32(s[j][1]);
            p1.x = f2tf32(s[j][2]); p1.y = f2tf32(s[j][3]);
            *(float2*)&Ps[ mrow      * AP + j * 8 + 2 * t] = p0;
            *(float2*)&Ps[(mrow + 8) * AP + j * 8 + 2 * t] = p1;
        }
        __syncwarp();

        // O += P V
#pragma unroll
        for (int ks = 0; ks < 8; ks++) {
            const int kb4 = ks * 32;
            uint32_t ap[4];
            ldsm4(ap, sbP + preA + kb4);
#pragma unroll
            for (int j2 = 0; j2 < 4; j2++) {
                uint32_t bf4[4];
                ldsm4(bf4, sbV + preB[j2] + kb4);
                mma_tf32(o[2 * j2],     ap, &bf4[0]);
                mma_tf32(o[2 * j2 + 1], ap, &bf4[2]);
            }
        }
        __syncwarp();
    }

    // write output
    const float inv0 = 1.0f / l_run[0];
    const float inv1 = 1.0f / l_run[1];
    float* orow0 = xout + ((size_t)b * NQ + q0 + mrow    ) * D_MODEL + hh * HDIM;
    float* orow1 = xout + ((size_t)b * NQ + q0 + mrow + 8) * D_MODEL + hh * HDIM;
#pragma unroll
    for (int j = 0; j < 8; j++) {
        float2 v0, v1;
        v0.x = o[j][0] * inv0; v0.y = o[j][1] * inv0;
        v1.x = o[j][2] * inv1; v1.y = o[j][3] * inv1;
        *(float2*)(orow0 + j * 8 + 2 * t) = v0;
        *(float2*)(orow1 + j * 8 + 2 * t) = v1;
    }
}

// ---------------- launch ----------------
extern "C" void kernel_launch(void* const* d_in, const int* in_sizes, int n_in,
                              void* d_out, int out_size) {
    const float* q     = (const float*)d_in[0];
    const float* kv    = (const float*)d_in[1];
    const void*  mask  = d_in[2];
    const float* Wq    = (const float*)d_in[3];
    const float* Wkv   = (const float*)d_in[4];
    const float* Wproj = (const float*)d_in[5];
    const float* bproj = (const float*)d_in[6];
    float* out = (float*)d_out;

    float *qp, *kmat, *vmat, *xbuf;
    cudaGetSymbolAddress((void**)&qp,   g_qp);
    cudaGetSymbolAddress((void**)&kmat, g_k);
    cudaGetSymbolAddress((void**)&vmat, g_v);
    cudaGetSymbolAddress((void**)&xbuf, g_x);

    cudaFuncSetAttribute(attn_mma,
                         cudaFuncAttributeMaxDynamicSharedMemorySize, ATT_SMEM);

    detect_mask_kernel<<<1, 256>>>((const unsigned int*)mask);

    // qp = 0.125 * (q @ Wq)
    sgemm_mma<<<dim3(D_MODEL / 128, (BATCH * NQ) / 128), 256>>>(
        q, Wq, qp, nullptr, BATCH * NQ, D_MODEL, D_MODEL, 0.125f, nullptr, 0);

    // kvp = kv @ Wkv, split into k / v
    sgemm_mma<<<dim3((2 * D_MODEL) / 128, (BATCH * NKV) / 128), 256>>>(
        kv, Wkv, kmat, vmat, BATCH * NKV, 2 * D_MODEL, D_MODEL, 1.0f, nullptr,
        D_MODEL);

    // attention (tf32 tensor cores + ldmatrix)
    attn_mma<<<dim3(NQ / 64, NHEADS, BATCH), 128, ATT_SMEM>>>(
        qp, kmat, vmat, mask, xbuf);

    // out = x @ Wproj + bproj
    sgemm_mma<<<dim3(D_MODEL / 128, (BATCH * NQ) / 128), 256>>>(
        xbuf, Wproj, out, nullptr, BATCH * NQ, D_MODEL, D_MODEL, 1.0f, bproj, 0);
}